// round 13
// baseline (speedup 1.0000x reference)
#include <cuda_runtime.h>
#include <cstdint>

#define TT 512
#define IDIM 512
#define H 1024
#define G 4096
#define NB 128
#define NT 288
#define FPAD 32    // one 128B line per counter
#define NGRP 32    // 4 blocks/counter -> 32 releases/iter/counter
#define WARES 22   // W_A rows resident in smem (of 32); rest streamed from L2

// ---------------- device scratch ----------------
__device__ __align__(16) float d_pre[(size_t)G * TT];       // W_ih_e@x_t + enc biases [r][t]
__device__ __align__(16) float d_EH[(size_t)(TT + 1) * H];  // eh rows; row0 = 0
__device__ __align__(16) float d_DH[(size_t)(TT + 1) * H];  // dh rows; row0 = 0
__device__ unsigned d_f[NGRP * FPAD];                       // padded group counters

__device__ __forceinline__ float sigf(float x) { return 1.f / (1.f + __expf(-x)); }
__device__ __forceinline__ float dot4(float4 a, float4 b) {
  return a.x * b.x + a.y * b.y + a.z * b.z + a.w * b.w;
}
__device__ __forceinline__ float wredsum(float v) {
#pragma unroll
  for (int o = 16; o; o >>= 1) v += __shfl_xor_sync(0xffffffffu, v, o);
  return v;
}
__device__ __forceinline__ float wredmax(float v) {
#pragma unroll
  for (int o = 16; o; o >>= 1) v = fmaxf(v, __shfl_xor_sync(0xffffffffu, v, o));
  return v;
}
__device__ __forceinline__ unsigned ld_acq(const unsigned* p) {
  unsigned v;
  asm volatile("ld.acquire.gpu.global.u32 %0, [%1];" : "=r"(v) : "l"(p) : "memory");
  return v;
}
__device__ __forceinline__ void red_rel(unsigned* p) {
  unsigned one = 1u;
  asm volatile("red.release.gpu.global.add.u32 [%0], %1;" :: "l"(p), "r"(one) : "memory");
}
__device__ __forceinline__ void poll_groups(const unsigned* flags, int lane, unsigned tgt) {
  const unsigned* p = flags + (size_t)lane * FPAD;
  for (;;) {
    unsigned v = ld_acq(p);
    if (__all_sync(0xffffffffu, v >= tgt)) break;
    __nanosleep(32);
  }
}

// ---------------- init ----------------
__global__ void init_state() {
  int i = blockIdx.x * blockDim.x + threadIdx.x;
  if (i < H) { d_EH[i] = 0.f; d_DH[i] = 0.f; }
  if (i < NGRP * FPAD) d_f[i] = 0u;
}

// ---------------- proven tiled GEMM: d_pre[r][t] = W_ih_e[r,:]·x_t + biases ----------------
#define BM 64
#define BN 64
#define BK 32
__global__ void __launch_bounds__(256) gemm_rowdot(const float* __restrict__ A, int lda,
                                                   const float* __restrict__ B, int ldb,
                                                   float* __restrict__ C, int K,
                                                   const float* __restrict__ bias0,
                                                   const float* __restrict__ bias1,
                                                   int hasBias) {
  __shared__ float As[BK][BM + 1];
  __shared__ float Bs[BK][BN + 1];
  int tid = threadIdx.x;
  int r0 = blockIdx.y * BM;
  int t0 = blockIdx.x * BN;
  int tx = tid & 15, ty = tid >> 4;
  float acc[4][4] = {};
  for (int k0 = 0; k0 < K; k0 += BK) {
#pragma unroll
    for (int i = 0; i < 8; ++i) {
      int lin = tid + i * 256;
      int m = lin >> 5, kk = lin & 31;
      As[kk][m] = A[(size_t)(r0 + m) * lda + k0 + kk];
      Bs[kk][m] = B[(size_t)(t0 + m) * ldb + k0 + kk];
    }
    __syncthreads();
#pragma unroll
    for (int kk = 0; kk < BK; ++kk) {
      float a[4], bv[4];
#pragma unroll
      for (int j = 0; j < 4; ++j) { a[j] = As[kk][ty * 4 + j]; bv[j] = Bs[kk][tx * 4 + j]; }
#pragma unroll
      for (int i2 = 0; i2 < 4; ++i2)
#pragma unroll
        for (int j = 0; j < 4; ++j) acc[i2][j] += a[i2] * bv[j];
    }
    __syncthreads();
  }
#pragma unroll
  for (int i2 = 0; i2 < 4; ++i2) {
    int r = r0 + ty * 4 + i2;
    float bias = hasBias ? (bias0[r] + bias1[r]) : 0.f;
#pragma unroll
    for (int j = 0; j < 4; ++j)
      C[(size_t)r * TT + (t0 + tx * 4 + j)] = acc[i2][j] + bias;
  }
}

// ---------------- fused pipelined persistent kernel (all fp32) ----------------
// smem floats: shWc [32][1024] | shWA [WARES][1024] | shEh 1024 | shDh 1024 | shS 16
#define SMEM_FLOATS (32 * 1024 + WARES * 1024 + 1024 + 1024 + 16)

__global__ void __launch_bounds__(NT, 1)
fused_persist(const float* __restrict__ Whh_e,
              const float* __restrict__ Wihd, const float* __restrict__ Whhd,
              const float* __restrict__ bihd, const float* __restrict__ bhhd,
              const float* __restrict__ Wattn, const float* __restrict__ battn) {
  extern __shared__ __align__(16) float sh[];
  float* shWc = sh;                              // 32768
  float* shWA = sh + 32 * 1024;                  // WARES*1024
  float* shEh = shWA + WARES * 1024;             // 1024
  float* shDh = shEh + 1024;                     // 1024
  float* shS  = shDh + 1024;                     // 16

  const int b = blockIdx.x, tid = threadIdx.x;
  const int w = tid >> 5, lane = tid & 31;
  const int u = b * 8 + w;           // unit (valid for w<8)
  unsigned* myflag = &d_f[(b >> 2) * FPAD];

  // ---- prologue: W_comb (all 32 rows) + W_A (first WARES rows) into smem ----
  for (int i = tid; i < 32 * 256; i += NT) {      // float4 granularity
    int jj = i >> 8, c4 = i & 255;
    int g = jj >> 3, wv = jj & 7;
    size_t r = (size_t)(b * 8 + wv) + (size_t)g * H;
    float4 x = __ldg((const float4*)(Wihd + r * (2 * H) + H) + c4);
    float4 y = __ldg((const float4*)(Whhd + r * H) + c4);
    ((float4*)shWc)[i] = make_float4(x.x + y.x, x.y + y.y, x.z + y.z, x.w + y.w);
  }
  for (int i = tid; i < WARES * 256; i += NT) {
    int jj = i >> 8, c4 = i & 255;
    int g = jj >> 3, wv = jj & 7;
    size_t r = (size_t)(b * 8 + wv) + (size_t)g * H;
    ((float4*)shWA)[i] = __ldg((const float4*)(Wihd + r * (2 * H)) + c4);
  }

  // ---- enc weights in regs + dec biases ----
  float4 wregE[4][8];
  float bd[4] = {0.f, 0.f, 0.f, 0.f};
  if (w < 8) {
#pragma unroll
    for (int g = 0; g < 4; ++g) {
      const float4* p = (const float4*)(Whh_e + (size_t)(u + g * H) * H);
#pragma unroll
      for (int c = 0; c < 8; ++c) wregE[g][c] = __ldg(p + c * 32 + lane);
      bd[g] = __ldg(bihd + u + g * H) + __ldg(bhhd + u + g * H);
    }
  }
  float awreg[16];                   // warp 8 softmax state
#pragma unroll
  for (int j = 0; j < 16; ++j) awreg[j] = 0.f;
  __syncthreads();

  float ec = 0.f, dc = 0.f;
  for (int i = 0; i <= TT; ++i) {
    const bool doEnc = (i < TT);
    const bool doDec = (i >= 1);
    const int t = i - 1;             // decoder step handled this iteration

    // ---- pre-poll prefetches ----
    float pre_g[4];
    float4 wrE[8], wrD[8];
    float bat = 0.f;
    if (w < 8) {
      if (doEnc && lane == 0) {
#pragma unroll
        for (int g = 0; g < 4; ++g) pre_g[g] = __ldg(&d_pre[(size_t)(u + g * H) * TT + i]);
      }
    } else {
      if (doDec) {
        const float4* wr = (const float4*)(Wattn + (size_t)t * (2 * H));
#pragma unroll
        for (int c = 0; c < 8; ++c) {
          wrE[c] = __ldg(wr + c * 32 + lane);
          wrD[c] = __ldg(wr + 256 + c * 32 + lane);
        }
        bat = __ldg(&battn[t]);
      }
      poll_groups(d_f, lane, 32u * (unsigned)i);
    }
    __syncthreads();   // S1: prev-iter stores visible; safe to restage

    if (tid < 256) {
      ((float4*)shEh)[tid] = __ldcg((const float4*)(d_EH + (size_t)i * H) + tid);
      if (doDec)
        ((float4*)shDh)[tid] = __ldcg((const float4*)(d_DH + (size_t)(i - 1) * H) + tid);
    }
    __syncthreads();   // S2: staged

    float aE[4] = {0.f, 0.f, 0.f, 0.f};
    float aD[4] = {0.f, 0.f, 0.f, 0.f};
    float pa[4] = {0.f, 0.f, 0.f, 0.f};
    if (w < 8) {
#pragma unroll
      for (int c = 0; c < 8; ++c) {
        float4 ehc = ((const float4*)shEh)[c * 32 + lane];
        if (doEnc) {
#pragma unroll
          for (int g = 0; g < 4; ++g) aE[g] += dot4(wregE[g][c], ehc);
        }
        if (doDec) {
          float4 dhc = ((const float4*)shDh)[c * 32 + lane];
#pragma unroll
          for (int g = 0; g < 4; ++g) {
            aD[g] += dot4(((const float4*)shWc)[(g * 8 + w) * 256 + c * 32 + lane], dhc);
            if (g * 8 + w < WARES)   // smem-resident W_A rows
              pa[g] += dot4(((const float4*)shWA)[(g * 8 + w) * 256 + c * 32 + lane], ehc);
          }
        }
      }
      if (doDec) {
        // streamed W_A rows (jj >= WARES) from L2
#pragma unroll
        for (int g = 0; g < 4; ++g) {
          if (g * 8 + w >= WARES) {
            const float4* pw = (const float4*)(Wihd + (size_t)(u + g * H) * (2 * H));
#pragma unroll
            for (int c = 0; c < 8; ++c)
              pa[g] += dot4(__ldg(pw + c * 32 + lane), ((const float4*)shEh)[c * 32 + lane]);
          }
        }
      }
      if (doEnc) {
#pragma unroll
        for (int g = 0; g < 4; ++g) aE[g] = wredsum(aE[g]);
      }
      if (doDec) {
#pragma unroll
        for (int g = 0; g < 4; ++g) { aD[g] = wredsum(aD[g]); pa[g] = wredsum(pa[g]); }
      }
    } else if (doDec) {
      // energy (both halves from staged vectors) + register softmax
      float e = 0.f;
#pragma unroll
      for (int c = 0; c < 8; ++c) {
        int idx = c * 32 + lane;
        e += dot4(wrE[c], ((const float4*)shEh)[idx]);
        e += dot4(wrD[c], ((const float4*)shDh)[idx]);
      }
      e = wredsum(e) + bat;
      float vals[16];
      float m = -1e30f;
#pragma unroll
      for (int j = 0; j < 16; ++j) {
        float x = (j * 32 + lane == t) ? e : awreg[j];
        vals[j] = x;
        m = fmaxf(m, x);
      }
      m = wredmax(m);
      float ssum = 0.f;
#pragma unroll
      for (int j = 0; j < 16; ++j) { vals[j] = __expf(vals[j] - m); ssum += vals[j]; }
      ssum = wredsum(ssum);
      float inv = 1.f / ssum;
#pragma unroll
      for (int j = 0; j < 16; ++j) awreg[j] = vals[j] * inv;
      if (lane == 0) shS[0] = __expf(e - m) * inv;
    }
    __syncthreads();   // S3: shS published; all dots done

    if (w < 8 && lane == 0) {
      if (doEnc) {
        float gi = aE[0] + pre_g[0], gf = aE[1] + pre_g[1];
        float gg = aE[2] + pre_g[2], go = aE[3] + pre_g[3];
        ec = sigf(gf) * ec + sigf(gi) * tanhf(gg);
        __stcg(&d_EH[(size_t)(i + 1) * H + u], sigf(go) * tanhf(ec));
      }
      if (doDec) {
        float s = shS[0];
        float gi = s * pa[0] + aD[0] + bd[0];
        float gf = s * pa[1] + aD[1] + bd[1];
        float gg = s * pa[2] + aD[2] + bd[2];
        float go = s * pa[3] + aD[3] + bd[3];
        dc = sigf(gf) * dc + sigf(gi) * tanhf(gg);
        __stcg(&d_DH[(size_t)i * H + u], sigf(go) * tanhf(dc));  // dh_{t+1} = dh_i
      }
      red_rel(myflag);   // one release per warp per iteration, unconditional
    }
  }
}

// ---------------- out[t] = Wout @ dh_{t+1} + bout ----------------
__global__ void out_final(const float* __restrict__ Wout, const float* __restrict__ bout,
                          float* __restrict__ out) {
  const int w = threadIdx.x >> 5, lane = threadIdx.x & 31;
  const int t = blockIdx.x * 8 + w;
  const float4* wo = (const float4*)Wout;
  const float4* dh = (const float4*)(d_DH + (size_t)(t + 1) * H);
  float o = 0.f;
#pragma unroll
  for (int c = 0; c < 8; ++c) o += dot4(__ldg(wo + c * 32 + lane), __ldcg(dh + c * 32 + lane));
  o = wredsum(o);
  if (lane == 0) out[t] = o + __ldg(bout);
}

// ---------------- launch ----------------
extern "C" void kernel_launch(void* const* d_in, const int* in_sizes, int n_in,
                              void* d_out, int out_size) {
  const float* input_seq = (const float*)d_in[0];
  const float* W_ih_e = (const float*)d_in[2];
  const float* W_hh_e = (const float*)d_in[3];
  const float* b_ih_e = (const float*)d_in[4];
  const float* b_hh_e = (const float*)d_in[5];
  const float* W_attn = (const float*)d_in[6];
  const float* b_attn = (const float*)d_in[7];
  const float* W_ih_d = (const float*)d_in[8];
  const float* W_hh_d = (const float*)d_in[9];
  const float* b_ih_d = (const float*)d_in[10];
  const float* b_hh_d = (const float*)d_in[11];
  const float* W_out  = (const float*)d_in[12];
  const float* b_out  = (const float*)d_in[13];
  float* out = (float*)d_out;

  float* pre_ptr = nullptr;
  cudaGetSymbolAddress((void**)&pre_ptr, d_pre);   // device address, NOT host shadow

  const int smem_bytes = SMEM_FLOATS * 4;          // 229,440 B
  cudaFuncSetAttribute(fused_persist, cudaFuncAttributeMaxDynamicSharedMemorySize, smem_bytes);

  init_state<<<8, 256>>>();
  gemm_rowdot<<<dim3(TT / BN, G / BM), 256>>>(W_ih_e, IDIM, input_seq, IDIM,
                                              pre_ptr, IDIM, b_ih_e, b_hh_e, 1);
  fused_persist<<<NB, NT, smem_bytes>>>(W_hh_e, W_ih_d, W_hh_d, b_ih_d, b_hh_d,
                                        W_attn, b_attn);
  out_final<<<TT / 8, 256>>>(W_out, b_out, out);
}

// round 14
// speedup vs baseline: 1.2589x; 1.2589x over previous
#include <cuda_runtime.h>
#include <cstdint>

#define TT 512
#define IDIM 512
#define H 1024
#define G 4096
#define NB 128
#define NT_ENC 256
#define NT_DEC 288
#define SENT 0x7FBFFFFFu   // signaling-NaN bit pattern; never produced by sig*tanh

// ---------------- device scratch ----------------
__device__ __align__(16) float d_pre[(size_t)G * TT];       // W_ih_e@x_t + biases   [r][t]
__device__ __align__(16) float d_PA[(size_t)G * TT];        // W_A @ eh_{t+1}        [r][t]
__device__ __align__(16) float d_EH[(size_t)(TT + 1) * H];  // eh rows; row0 = 0, rest sentinel
__device__ __align__(16) float d_DH[(size_t)(TT + 1) * H];  // dh rows; row0 = 0, rest sentinel

__device__ __forceinline__ float sigf(float x) { return 1.f / (1.f + __expf(-x)); }
__device__ __forceinline__ float dot4(float4 a, float4 b) {
  return a.x * b.x + a.y * b.y + a.z * b.z + a.w * b.w;
}
__device__ __forceinline__ float wredsum(float v) {
#pragma unroll
  for (int o = 16; o; o >>= 1) v += __shfl_xor_sync(0xffffffffu, v, o);
  return v;
}
__device__ __forceinline__ float wredmax(float v) {
#pragma unroll
  for (int o = 16; o; o >>= 1) v = fmaxf(v, __shfl_xor_sync(0xffffffffu, v, o));
  return v;
}
__device__ __forceinline__ uint4 ld_cg_u4(const uint4* p) {
  uint4 v;
  asm volatile("ld.global.cg.v4.u32 {%0,%1,%2,%3}, [%4];"
               : "=r"(v.x), "=r"(v.y), "=r"(v.z), "=r"(v.w) : "l"(p) : "memory");
  return v;
}
// spin until this thread's float4 has no sentinel words (data IS the flag)
__device__ __forceinline__ uint4 poll_row4(const uint4* p) {
  uint4 v = ld_cg_u4(p);
  while (v.x == SENT || v.y == SENT || v.z == SENT || v.w == SENT) {
    __nanosleep(40);
    v = ld_cg_u4(p);
  }
  return v;
}

// ---------------- init: row0 = 0, rows 1..TT = sentinel ----------------
__global__ void init_state() {
  const int n = (TT + 1) * H;
  for (int i = blockIdx.x * blockDim.x + threadIdx.x; i < n; i += gridDim.x * blockDim.x) {
    unsigned v = (i < H) ? 0u : SENT;     // 0u == 0.0f
    ((unsigned*)d_EH)[i] = v;
    ((unsigned*)d_DH)[i] = v;
  }
}

// ---------------- proven tiled GEMM: C[r][t] = A[r,:K]·B[t,:K] (+bias) ----------------
#define BM 64
#define BN 64
#define BK 32
__global__ void __launch_bounds__(256) gemm_rowdot(const float* __restrict__ A, int lda,
                                                   const float* __restrict__ B, int ldb,
                                                   float* __restrict__ C, int K,
                                                   const float* __restrict__ bias0,
                                                   const float* __restrict__ bias1,
                                                   int hasBias) {
  __shared__ float As[BK][BM + 1];
  __shared__ float Bs[BK][BN + 1];
  int tid = threadIdx.x;
  int r0 = blockIdx.y * BM;
  int t0 = blockIdx.x * BN;
  int tx = tid & 15, ty = tid >> 4;
  float acc[4][4] = {};
  for (int k0 = 0; k0 < K; k0 += BK) {
#pragma unroll
    for (int i = 0; i < 8; ++i) {
      int lin = tid + i * 256;
      int m = lin >> 5, kk = lin & 31;
      As[kk][m] = A[(size_t)(r0 + m) * lda + k0 + kk];
      Bs[kk][m] = B[(size_t)(t0 + m) * ldb + k0 + kk];
    }
    __syncthreads();
#pragma unroll
    for (int kk = 0; kk < BK; ++kk) {
      float a[4], bv[4];
#pragma unroll
      for (int j = 0; j < 4; ++j) { a[j] = As[kk][ty * 4 + j]; bv[j] = Bs[kk][tx * 4 + j]; }
#pragma unroll
      for (int i2 = 0; i2 < 4; ++i2)
#pragma unroll
        for (int j = 0; j < 4; ++j) acc[i2][j] += a[i2] * bv[j];
    }
    __syncthreads();
  }
#pragma unroll
  for (int i2 = 0; i2 < 4; ++i2) {
    int r = r0 + ty * 4 + i2;
    float bias = hasBias ? (bias0[r] + bias1[r]) : 0.f;
#pragma unroll
    for (int j = 0; j < 4; ++j)
      C[(size_t)r * TT + (t0 + tx * 4 + j)] = acc[i2][j] + bias;
  }
}

// ---------------- encoder persistent: sentinel-sync, no flags ----------------
__global__ void __launch_bounds__(NT_ENC, 1)
enc_persist(const float* __restrict__ Whh_e) {
  __shared__ __align__(16) float shEh[H];
  const int b = blockIdx.x, tid = threadIdx.x;
  const int w = tid >> 5, lane = tid & 31;
  const int u = b * 8 + w;

  float4 wreg[4][8];
#pragma unroll
  for (int g = 0; g < 4; ++g) {
    const float4* p = (const float4*)(Whh_e + (size_t)(u + g * H) * H);
#pragma unroll
    for (int c = 0; c < 8; ++c) wreg[g][c] = __ldg(p + c * 32 + lane);
  }

  float ec = 0.f;
  for (int t = 0; t < TT; ++t) {
    float pre_g[4];
    if (lane == 0) {
#pragma unroll
      for (int g = 0; g < 4; ++g) pre_g[g] = __ldg(&d_pre[(size_t)(u + g * H) * TT + t]);
    }
    // stage row t: each thread spins on ITS float4 until fully written
    uint4 hv4 = poll_row4((const uint4*)(d_EH + (size_t)t * H) + tid);
    ((uint4*)shEh)[tid] = hv4;
    __syncthreads();   // S2: staged

    float a[4] = {0.f, 0.f, 0.f, 0.f};
#pragma unroll
    for (int c = 0; c < 8; ++c) {
      float4 hv = ((const float4*)shEh)[c * 32 + lane];
#pragma unroll
      for (int g = 0; g < 4; ++g) a[g] += dot4(wreg[g][c], hv);
    }
#pragma unroll
    for (int g = 0; g < 4; ++g) a[g] = wredsum(a[g]);
    if (lane == 0) {
      float gi = a[0] + pre_g[0], gf = a[1] + pre_g[1];
      float gg = a[2] + pre_g[2], go = a[3] + pre_g[3];
      ec = sigf(gf) * ec + sigf(gi) * tanhf(gg);
      __stcg(&d_EH[(size_t)(t + 1) * H + u], sigf(go) * tanhf(ec));   // data IS the flag
    }
    __syncthreads();   // S3: all reads of shEh done before next-iter overwrite
  }
}

// ---------------- decoder persistent: sentinel-sync ----------------
__global__ void __launch_bounds__(NT_DEC, 1)
dec_persist(const float* __restrict__ Wihd, const float* __restrict__ Whhd,
            const float* __restrict__ bihd, const float* __restrict__ bhhd,
            const float* __restrict__ Wattn, const float* __restrict__ battn) {
  __shared__ __align__(16) float shDh[H];
  __shared__ float shS[4];
  const int b = blockIdx.x, tid = threadIdx.x;
  const int w = tid >> 5, lane = tid & 31;
  const int u = b * 8 + w;           // valid for w<8

  float4 wreg[4][8];                 // W_ih_d[:,H:] + W_hh_d rows (dh coefficients)
  float bd[4] = {0.f, 0.f, 0.f, 0.f};
  if (w < 8) {
#pragma unroll
    for (int g = 0; g < 4; ++g) {
      const int row = u + g * H;
      const float4* pA = (const float4*)(Wihd + (size_t)row * (2 * H) + H);
      const float4* pB = (const float4*)(Whhd + (size_t)row * H);
#pragma unroll
      for (int c = 0; c < 8; ++c) {
        float4 x = __ldg(pA + c * 32 + lane), y = __ldg(pB + c * 32 + lane);
        wreg[g][c] = make_float4(x.x + y.x, x.y + y.y, x.z + y.z, x.w + y.w);
      }
      bd[g] = __ldg(bihd + row) + __ldg(bhhd + row);
    }
  }
  float awreg[16];                   // warp 8: softmaxed attention weights
#pragma unroll
  for (int j = 0; j < 16; ++j) awreg[j] = 0.f;
  __syncthreads();

  float dc = 0.f;
  for (int t = 0; t < TT; ++t) {
    // prefetches (static wrt this step)
    float pa_g[4];
    float eEH = 0.f, bat = 0.f;
    if (w < 8) {
      if (lane == 0) {
#pragma unroll
        for (int g = 0; g < 4; ++g) pa_g[g] = __ldg(&d_PA[(size_t)(u + g * H) * TT + t]);
      }
      // stage dh row t: spin on own float4 (warps 0-7 = 256 threads cover the row)
      uint4 hv4 = poll_row4((const uint4*)(d_DH + (size_t)t * H) + tid);
      ((uint4*)shDh)[tid] = hv4;
    } else {
      // warp 8: eh-half of energy (eh fully materialized; no poll needed)
      const float4* wrE = (const float4*)(Wattn + (size_t)t * (2 * H));
      const float4* ehp = (const float4*)(d_EH + (size_t)(t + 1) * H);
#pragma unroll
      for (int c = 0; c < 8; ++c)
        eEH += dot4(__ldg(wrE + c * 32 + lane), __ldcg(ehp + c * 32 + lane));
      bat = __ldg(&battn[t]);
    }
    __syncthreads();   // S2: shDh staged

    float a[4] = {0.f, 0.f, 0.f, 0.f};
    if (w < 8) {
#pragma unroll
      for (int c = 0; c < 8; ++c) {
        float4 dhc = ((const float4*)shDh)[c * 32 + lane];
#pragma unroll
        for (int g = 0; g < 4; ++g) a[g] += dot4(wreg[g][c], dhc);
      }
#pragma unroll
      for (int g = 0; g < 4; ++g) a[g] = wredsum(a[g]);
    } else {
      // dh-half of energy + register-resident softmax
      const float4* wrD = (const float4*)(Wattn + (size_t)t * (2 * H)) + 256;
      float e = eEH;
#pragma unroll
      for (int c = 0; c < 8; ++c) {
        int idx = c * 32 + lane;
        e += dot4(__ldg(wrD + idx), ((const float4*)shDh)[idx]);
      }
      e = wredsum(e) + bat;
      float vals[16];
      float m = -1e30f;
#pragma unroll
      for (int j = 0; j < 16; ++j) {
        float x = (j * 32 + lane == t) ? e : awreg[j];
        vals[j] = x;
        m = fmaxf(m, x);
      }
      m = wredmax(m);
      float ssum = 0.f;
#pragma unroll
      for (int j = 0; j < 16; ++j) { vals[j] = __expf(vals[j] - m); ssum += vals[j]; }
      ssum = wredsum(ssum);
      float inv = 1.f / ssum;
#pragma unroll
      for (int j = 0; j < 16; ++j) awreg[j] = vals[j] * inv;
      if (lane == 0) shS[0] = __expf(e - m) * inv;
    }
    __syncthreads();   // S3: shS published

    if (w < 8 && lane == 0) {
      float s = shS[0];
      float gi = s * pa_g[0] + a[0] + bd[0];
      float gf = s * pa_g[1] + a[1] + bd[1];
      float gg = s * pa_g[2] + a[2] + bd[2];
      float go = s * pa_g[3] + a[3] + bd[3];
      dc = sigf(gf) * dc + sigf(gi) * tanhf(gg);
      __stcg(&d_DH[(size_t)(t + 1) * H + u], sigf(go) * tanhf(dc));  // data IS the flag
    }
    __syncthreads();   // S4: shDh reads done before next-iter overwrite
  }
}

// ---------------- out[t] = Wout @ dh_{t+1} + bout ----------------
__global__ void out_final(const float* __restrict__ Wout, const float* __restrict__ bout,
                          float* __restrict__ out) {
  const int w = threadIdx.x >> 5, lane = threadIdx.x & 31;
  const int t = blockIdx.x * 8 + w;
  const float4* wo = (const float4*)Wout;
  const float4* dh = (const float4*)(d_DH + (size_t)(t + 1) * H);
  float o = 0.f;
#pragma unroll
  for (int c = 0; c < 8; ++c) o += dot4(__ldg(wo + c * 32 + lane), __ldcg(dh + c * 32 + lane));
  o = wredsum(o);
  if (lane == 0) out[t] = o + __ldg(bout);
}

// ---------------- launch ----------------
extern "C" void kernel_launch(void* const* d_in, const int* in_sizes, int n_in,
                              void* d_out, int out_size) {
  const float* input_seq = (const float*)d_in[0];
  const float* W_ih_e = (const float*)d_in[2];
  const float* W_hh_e = (const float*)d_in[3];
  const float* b_ih_e = (const float*)d_in[4];
  const float* b_hh_e = (const float*)d_in[5];
  const float* W_attn = (const float*)d_in[6];
  const float* b_attn = (const float*)d_in[7];
  const float* W_ih_d = (const float*)d_in[8];
  const float* W_hh_d = (const float*)d_in[9];
  const float* b_ih_d = (const float*)d_in[10];
  const float* b_hh_d = (const float*)d_in[11];
  const float* W_out  = (const float*)d_in[12];
  const float* b_out  = (const float*)d_in[13];
  float* out = (float*)d_out;

  // device-global symbols must be resolved via cudaGetSymbolAddress (host shadow trap)
  float *pre_ptr = nullptr, *pa_ptr = nullptr, *eh_ptr = nullptr;
  cudaGetSymbolAddress((void**)&pre_ptr, d_pre);
  cudaGetSymbolAddress((void**)&pa_ptr,  d_PA);
  cudaGetSymbolAddress((void**)&eh_ptr,  d_EH);

  init_state<<<256, 256>>>();
  gemm_rowdot<<<dim3(TT / BN, G / BM), 256>>>(W_ih_e, IDIM, input_seq, IDIM,
                                              pre_ptr, IDIM, b_ih_e, b_hh_e, 1);
  enc_persist<<<NB, NT_ENC>>>(W_hh_e);
  gemm_rowdot<<<dim3(TT / BN, G / BM), 256>>>(W_ih_d, 2 * H, eh_ptr + H, H,
                                              pa_ptr, H, nullptr, nullptr, 0);
  dec_persist<<<NB, NT_DEC>>>(W_ih_d, W_hh_d, b_ih_d, b_hh_d, W_attn, b_attn);
  out_final<<<TT / 8, 256>>>(W_out, b_out, out);
}